// round 17
// baseline (speedup 1.0000x reference)
#include <cuda_runtime.h>

// ChamferDistance: B=8, N=M=8192, D=3.
// BISECTION ROUND: R14's proven kernel structure (passed, rel_err 8e-8),
// with the single change that owned points and opposing tiles come from the
// z-sorted g_sorted array (permutation of the input; mins/sums invariant).
// No pruning. Validates the sorted-data path in isolation.

#define PTS      8192
#define SEGS     16                  // (batch<<1) | set ; opposing seg = seg^1
#define NB       512                 // z bins for counting sort
#define BOXMIN   (-8.0f)
#define INVW     32.0f               // NB / 16
#define TPB      256
#define RX       4
#define CHUNK    (TPB * RX)          // 1024 owned points per group
#define NCHUNK   (PTS / CHUNK)       // 8
#define NJS      8                   // j-slices per group
#define JSEG     (PTS / NJS)         // 1024 opposing points per block
#define TILE     JSEG
#define JP       (TILE / 2)          // 512 j-pairs per tile
#define NGROUP   (SEGS * NCHUNK)     // 128
#define NBLOCKS  (NGROUP * NJS)      // 1024

__device__ float4   g_sorted[SEGS * PTS];   // (x,y,z,|p|^2), z-bin sorted
__device__ float    g_pmin[NGROUP * NJS * CHUNK];   // 4.2 MB scratch
__device__ float    g_part[NGROUP];
__device__ unsigned g_gticket[NGROUP];
__device__ unsigned g_fticket;

#define PACK_F32X2(out, lo, hi) \
    asm("mov.b64 %0, {%1, %2};" : "=l"(out) : "f"(lo), "f"(hi))
#define UNPACK_F32X2(lo, hi, in) \
    asm("mov.b64 {%0, %1}, %2;" : "=f"(lo), "=f"(hi) : "l"(in))
#define FMA_F32X2(d, a, b, c) \
    asm("fma.rn.f32x2 %0, %1, %2, %3;" : "=l"(d) : "l"(a), "l"(b), "l"(c))

__device__ __forceinline__ int binof(float v) {
    int b = (int)floorf((v - BOXMIN) * INVW);
    return min(max(b, 0), NB - 1);
}

// ---- 1. per-segment z counting sort, payload (x,y,z,|p|^2) ----
__global__ __launch_bounds__(TPB)
void k_sort(const float* __restrict__ x, const float* __restrict__ y) {
    __shared__ unsigned cnt[NB];
    __shared__ unsigned off[NB + 1];
    __shared__ unsigned scn[TPB];

    const int seg = blockIdx.x;
    const int tid = threadIdx.x;
    const float* __restrict__ base =
        ((seg & 1) ? y : x) + (size_t)(seg >> 1) * PTS * 3;

    for (int i = tid; i < NB; i += TPB) cnt[i] = 0;
    __syncthreads();
    for (int i = tid; i < PTS; i += TPB)
        atomicAdd(&cnt[binof(base[i * 3 + 2])], 1u);
    __syncthreads();

    // exclusive scan of 512 bins (2 per thread + Hillis-Steele block scan)
    unsigned v0 = cnt[2 * tid], v1 = cnt[2 * tid + 1];
    unsigned s = v0 + v1;
    scn[tid] = s;
    __syncthreads();
#pragma unroll
    for (int o = 1; o < TPB; o <<= 1) {
        unsigned t = (tid >= o) ? scn[tid - o] : 0u;
        __syncthreads();
        if (tid >= o) scn[tid] += t;
        __syncthreads();
    }
    unsigned excl = scn[tid] - s;
    off[2 * tid]     = excl;
    off[2 * tid + 1] = excl + v0;
    if (tid == TPB - 1) off[NB] = scn[TPB - 1];
    __syncthreads();

    for (int i = tid; i < NB; i += TPB) cnt[i] = 0;   // reuse as cursor
    __syncthreads();

    for (int i = tid; i < PTS; i += TPB) {
        float a = base[i * 3 + 0];
        float b = base[i * 3 + 1];
        float c = base[i * 3 + 2];
        int bb = binof(c);
        unsigned pos = off[bb] + atomicAdd(&cnt[bb], 1u);
        g_sorted[seg * PTS + pos] =
            make_float4(a, b, c, fmaf(a, a, fmaf(b, b, c * c)));
    }
}

// ---- 2. R14 pass kernel over sorted data (no pruning) ----
__global__ __launch_bounds__(TPB)
void chamfer_pass_kernel(float* __restrict__ out) {
    const int bid   = blockIdx.x;
    const int seg   = bid >> 6;            // 0..15
    const int local = bid & 63;
    const int chunk = local >> 3;          // 0..7
    const int js    = local & 7;           // 0..7
    const int group = seg * NCHUNK + chunk;        // 0..127

    const float4* __restrict__ own = g_sorted + seg       * PTS;
    const float4* __restrict__ opp = g_sorted + (seg ^ 1) * PTS;

    // Per j-pair: sAB = {(-2a0,-2a1),(-2b0,-2b1)}, sCN = {(-2c0,-2c1),(n0,n1)}
    __shared__ __align__(16) ulonglong2 sAB[JP];
    __shared__ __align__(16) ulonglong2 sCN[JP];

    const int tid = threadIdx.x;

    // Owned points: coordinate broadcast into both f32x2 lanes; qw = |q|^2.
    unsigned long long xa[RX], xb[RX], xc[RX];
    float qw[RX], mnl[RX], mnh[RX];
#pragma unroll
    for (int r = 0; r < RX; r++) {
        float4 q = own[chunk * CHUNK + r * TPB + tid];
        PACK_F32X2(xa[r], q.x, q.x);
        PACK_F32X2(xb[r], q.y, q.y);
        PACK_F32X2(xc[r], q.z, q.z);
        qw[r] = q.w;
        mnl[r] = 3.4e38f;
        mnh[r] = 3.4e38f;
    }

    // single tile fill (JSEG == TILE), -2 folded into opposing coords
    {
        const int jbase = js * JSEG;
#pragma unroll
        for (int jj = tid; jj < TILE; jj += TPB) {
            float4 p = opp[jbase + jj];
            int jp = jj >> 1, lane = jj & 1;
            float* pab = (float*)&sAB[jp];
            float* pcn = (float*)&sCN[jp];
            pab[lane + 0] = -2.0f * p.x;
            pab[lane + 2] = -2.0f * p.y;
            pcn[lane + 0] = -2.0f * p.z;
            pcn[lane + 2] = p.w;
        }
        __syncthreads();

#pragma unroll 8
        for (int jp = 0; jp < JP; ++jp) {
            ulonglong2 ab = sAB[jp];   // LDS.128 broadcast
            ulonglong2 cn = sCN[jp];   // LDS.128 broadcast
#pragma unroll
            for (int r = 0; r < RX; ++r) {
                unsigned long long t;
                FMA_F32X2(t, xc[r], cn.x, cn.y);
                FMA_F32X2(t, xb[r], ab.y, t);
                FMA_F32X2(t, xa[r], ab.x, t);
                float lo, hi;
                UNPACK_F32X2(lo, hi, t);
                mnl[r] = fminf(mnl[r], lo);
                mnh[r] = fminf(mnh[r], hi);
            }
        }
    }

    // publish this j-slice's partial mins
#pragma unroll
    for (int r = 0; r < RX; r++)
        g_pmin[(group * NJS + js) * CHUNK + r * TPB + tid] = fminf(mnl[r], mnh[r]);

    // per-group ticket: 8th arrival combines (fixed order -> deterministic)
    __shared__ bool isComb;
    __threadfence();
    __syncthreads();
    if (tid == 0) {
        unsigned t = atomicAdd(&g_gticket[group], 1u);
        isComb = (t == NJS - 1);
        if (isComb) g_gticket[group] = 0;   // reset for next replay
    }
    __syncthreads();
    if (!isComb) return;
    __threadfence();

    float s = 0.0f;
#pragma unroll
    for (int r = 0; r < RX; r++) {
        int idx = r * TPB + tid;
        float m = 3.4e38f;
#pragma unroll
        for (int ss = 0; ss < NJS; ss++)
            m = fminf(m, g_pmin[(group * NJS + ss) * CHUNK + idx]);
        s += m + qw[r];
    }

    __shared__ float red[TPB];
    red[tid] = s;
    __syncthreads();
#pragma unroll
    for (int o = TPB / 2; o > 0; o >>= 1) {
        if (tid < o) red[tid] += red[tid + o];
        __syncthreads();
    }
    if (tid == 0) g_part[group] = red[0];

    // global ticket over the 128 combiners: last one reduces the scalar
    __shared__ bool isFin;
    __threadfence();
    __syncthreads();
    if (tid == 0) {
        unsigned t = atomicAdd(&g_fticket, 1u);
        isFin = (t == NGROUP - 1);
        if (isFin) g_fticket = 0;   // reset for next replay
    }
    __syncthreads();
    if (!isFin) return;
    __threadfence();

    float v = (tid < NGROUP) ? g_part[tid] : 0.0f;
    red[tid] = v;
    __syncthreads();
#pragma unroll
    for (int o = TPB / 2; o > 0; o >>= 1) {
        if (tid < o) red[tid] += red[tid + o];
        __syncthreads();
    }
    if (tid == 0) out[0] = red[0] * (1.0f / 65536.0f);
}

extern "C" void kernel_launch(void* const* d_in, const int* in_sizes, int n_in,
                              void* d_out, int out_size) {
    const float* x = (const float*)d_in[0];
    const float* y = (const float*)d_in[1];
    float* out = (float*)d_out;

    k_sort            <<<SEGS, TPB>>>(x, y);
    chamfer_pass_kernel<<<NBLOCKS, TPB>>>(out);
}